// round 16
// baseline (speedup 1.0000x reference)
#include <cuda_runtime.h>
#include <cuda_fp16.h>
#include <math.h>
#include <stdint.h>

// ---------------- problem constants ----------------
#define cB  32
#define cU  64
#define cP  8
#define cV  32000
#define cD  300
#define cL  256
#define cH  5
#define cS  5
#define cNT 2304
#define cNU 2048
#define cNQ 256
#define cE  8128
#define cNC 1200
#define ZD  1500
#define PKL 1810
#define PKW 1824
#define KPAD 304
#define K2R 150

// ---------------- scratch (device globals) ----------------
__device__ __half  g_Ah[(size_t)cV * KPAD];
__device__ __half  g_WPh[(size_t)cV * cNC];      // 76.8 MB, L2-resident
__device__ __half2 g_WcatI[K2R * cNC];
__device__ __half2 g_WpackI[cS * K2R * PKW];
__device__ float   g_bmean[cS * cD];
__device__ __half  g_h0[cNT * KPAD];
__device__ __half  g_h1[cNT * KPAD];
__device__ __half  g_ZRh[(size_t)cNT * PKW];
__device__ __half2 g_poolpart[4][cNU][152];
__device__ int     g_csr_off[cNT + 1];
__device__ int     g_csr_edge[cE];

// ---------------- fused prep mega-kernel ----------------
// sections: w2h | wcat | pack_z | pack_rmean | pack_elr | pack_pad | bias |
//           hzero_pads | partyfeat | csr(1 block)
#define NB(x) (((x) + 255) / 256)
#define PREP_A NB(cV * KPAD)
#define PREP_B NB(K2R * cNC)
#define PREP_C NB(cS * K2R * ZD)
#define PREP_D NB(cS * K2R * cD)
#define PREP_E NB(cS * K2R * cH * 2 * 32)
#define PREP_F NB(cS * K2R * (PKW - PKL))
#define PREP_G NB(cS * cD)
#define PREP_H NB(cNT * (KPAD - cD) * 2)
#define PREP_I NB(cNQ * cD)
#define PREP_J 1
#define PREP_TOTAL (PREP_A+PREP_B+PREP_C+PREP_D+PREP_E+PREP_F+PREP_G+PREP_H+PREP_I+PREP_J)

__device__ __forceinline__ float wcat_val(const float* w3, const float* w4,
                                          const float* w5, int k, int c) {
    if (c < 300)      { int t = c / 100,        f = c % 100;          return w3[(f * 3 + t) * cD + k]; }
    else if (c < 700) { int t = (c - 300) / 100, f = (c - 300) % 100; return w4[(f * 4 + t) * cD + k]; }
    else              { int t = (c - 700) / 100, f = (c - 700) % 100; return w5[(f * 5 + t) * cD + k]; }
}

__global__ __launch_bounds__(256) void prep(
        const float* __restrict__ word_W,
        const float* __restrict__ w3, const float* __restrict__ w4,
        const float* __restrict__ w5,
        const float* __restrict__ fc, const float* __restrict__ res,
        const float* __restrict__ al, const float* __restrict__ ar,
        const float* __restrict__ gb,
        const int* __restrict__ q_idx, const int* __restrict__ pids,
        const float* __restrict__ party_W,
        const int* __restrict__ dst) {
    __shared__ int cnt[cNT];
    __shared__ int off[cNT];
    __shared__ int ws[256];
    int bid = blockIdx.x, tid = threadIdx.x;
    if (bid < PREP_A) {                                   // w2h
        int i = bid * 256 + tid;
        if (i < cV * KPAD) {
            int r = i / KPAD, k = i % KPAD;
            g_Ah[i] = (k < cD) ? __float2half(word_W[(size_t)r * cD + k]) : __half(0.f);
        }
        return;
    }
    bid -= PREP_A;
    if (bid < PREP_B) {                                   // wcat
        int i = bid * 256 + tid;
        if (i < K2R * cNC) {
            int k2 = i / cNC, c = i % cNC;
            g_WcatI[i] = __floats2half2_rn(wcat_val(w3, w4, w5, 2 * k2, c),
                                           wcat_val(w3, w4, w5, 2 * k2 + 1, c));
        }
        return;
    }
    bid -= PREP_B;
    if (bid < PREP_C) {                                   // pack_z
        int i = bid * 256 + tid;
        if (i < cS * K2R * ZD) {
            int s = i / (K2R * ZD);
            int k2 = (i / ZD) % K2R;
            int c = i % ZD;
            const float* f0 = fc + (size_t)s * cD * ZD + (size_t)(2 * k2) * ZD;
            g_WpackI[(size_t)(s * K2R + k2) * PKW + c] = __floats2half2_rn(f0[c], f0[ZD + c]);
        }
        return;
    }
    bid -= PREP_C;
    if (bid < PREP_D) {                                   // pack_rmean
        int i = bid * 256 + tid;
        if (i < cS * K2R * cD) {
            int s = i / (K2R * cD);
            int k2 = (i / cD) % K2R;
            int d = i % cD;
            const float* r0 = res + (size_t)s * cD * ZD + (size_t)(2 * k2) * ZD;
            float s0 = 0.f, s1 = 0.f;
#pragma unroll
            for (int h = 0; h < cH; h++) { s0 += r0[h * cD + d]; s1 += r0[ZD + h * cD + d]; }
            g_WpackI[(size_t)(s * K2R + k2) * PKW + ZD + d] =
                __floats2half2_rn(0.2f * s0, 0.2f * s1);
        }
        return;
    }
    bid -= PREP_D;
    if (bid < PREP_E) {                                   // pack_elr
        int w = (bid * 256 + tid) >> 5;
        int lane = tid & 31;
        if (w < cS * K2R * cH * 2) {
            int side = w & 1;
            int h = (w >> 1) % cH;
            int k2 = (w >> 1) / cH % K2R;
            int s = (w >> 1) / (cH * K2R);
            const float* av = (side ? ar : al) + (size_t)s * cH * cD + h * cD;
            const float* f0 = fc + (size_t)s * cD * ZD + (size_t)(2 * k2) * ZD + h * cD;
            float s0 = 0.f, s1 = 0.f;
            for (int d = lane; d < cD; d += 32) {
                float a = av[d];
                s0 += f0[d] * a;
                s1 += f0[ZD + d] * a;
            }
#pragma unroll
            for (int o = 16; o; o >>= 1) {
                s0 += __shfl_xor_sync(0xffffffffu, s0, o);
                s1 += __shfl_xor_sync(0xffffffffu, s1, o);
            }
            if (lane == 0)
                g_WpackI[(size_t)(s * K2R + k2) * PKW + ZD + cD + side * cH + h] =
                    __floats2half2_rn(s0, s1);
        }
        return;
    }
    bid -= PREP_E;
    if (bid < PREP_F) {                                   // pack_pad
        int i = bid * 256 + tid;
        if (i < cS * K2R * (PKW - PKL)) {
            int s = i / (K2R * (PKW - PKL));
            int k2 = (i / (PKW - PKL)) % K2R;
            int c = i % (PKW - PKL);
            g_WpackI[(size_t)(s * K2R + k2) * PKW + PKL + c] = __floats2half2_rn(0.f, 0.f);
        }
        return;
    }
    bid -= PREP_F;
    if (bid < PREP_G) {                                   // bias_mean
        int i = bid * 256 + tid;
        if (i < cS * cD) {
            int s = i / cD, d = i % cD;
            float sum = 0.f;
#pragma unroll
            for (int h = 0; h < cH; h++) sum += gb[s * ZD + h * cD + d];
            g_bmean[i] = 0.2f * sum;
        }
        return;
    }
    bid -= PREP_G;
    if (bid < PREP_H) {                                   // hzero_pads
        int i = bid * 256 + tid;
        if (i < cNT * (KPAD - cD) * 2) {
            int buf = i & 1;
            int j = i >> 1;
            int n = j / (KPAD - cD), d = cD + j % (KPAD - cD);
            (buf ? g_h1 : g_h0)[(size_t)n * KPAD + d] = __half(0.f);
        }
        return;
    }
    bid -= PREP_H;
    if (bid < PREP_I) {                                   // party features
        int i = bid * 256 + tid;
        if (i < cNQ * cD) {
            int j = i / cD, d = i % cD;
            g_h0[(size_t)q_idx[j] * KPAD + d] = __float2half(party_W[pids[j] * cD + d]);
        }
        return;
    }
    // ---- csr build (single block, block-local syncs) ----
    {
        int t = tid;
        for (int i = t; i < cNT; i += 256) cnt[i] = 0;
        __syncthreads();
        for (int e = t; e < cE; e += 256) atomicAdd(&cnt[dst[e]], 1);
        __syncthreads();
        int base = t * 9;
        int c[9]; int sum = 0;
#pragma unroll
        for (int j = 0; j < 9; j++) { c[j] = sum; sum += cnt[base + j]; }
        ws[t] = sum;
        __syncthreads();
        for (int o = 1; o < 256; o <<= 1) {
            int v = (t >= o) ? ws[t - o] : 0;
            __syncthreads();
            ws[t] += v;
            __syncthreads();
        }
        int pre = ws[t] - sum;
#pragma unroll
        for (int j = 0; j < 9; j++) { off[base + j] = pre + c[j]; g_csr_off[base + j] = pre + c[j]; }
        if (t == 255) g_csr_off[cNT] = pre + sum;
        __syncthreads();
        for (int i = t; i < cNT; i += 256) cnt[i] = 0;
        __syncthreads();
        for (int e = t; e < cE; e += 256) {
            int dn = dst[e];
            int p = off[dn] + atomicAdd(&cnt[dn], 1);
            g_csr_edge[p] = e;
        }
    }
}

// ---------------- fp16 GEMM helpers ----------------
__device__ __forceinline__ void mma16(float* c, const uint32_t* a, uint32_t b0, uint32_t b1) {
    asm volatile(
        "mma.sync.aligned.m16n8k16.row.col.f32.f16.f16.f32 "
        "{%0,%1,%2,%3},{%4,%5,%6,%7},{%8,%9},{%0,%1,%2,%3};"
        : "+f"(c[0]), "+f"(c[1]), "+f"(c[2]), "+f"(c[3])
        : "r"(a[0]), "r"(a[1]), "r"(a[2]), "r"(a[3]), "r"(b0), "r"(b1));
}
__device__ __forceinline__ void cpasync16(uint32_t dst, const void* src, bool valid) {
    int sz = valid ? 16 : 0;
    asm volatile("cp.async.ca.shared.global [%0], [%1], 16, %2;"
                 :: "r"(dst), "l"(src), "r"(sz));
}
__device__ __forceinline__ void cp_commit() { asm volatile("cp.async.commit_group;"); }
template<int N>
__device__ __forceinline__ void cp_wait() { asm volatile("cp.async.wait_group %0;" :: "n"(N)); }

// ---------------- fp16 tensor-core GEMM, cp.async 2-stage ----------------
#define SA_STR 40
#define SB_STR 132
__global__ __launch_bounds__(256, 2) void gemm_f16(
        const __half* __restrict__ A, const __half2* __restrict__ Bi,
        __half* __restrict__ Ch, int M, int N) {
    __shared__ __align__(16) __half  sA[2][128][SA_STR];
    __shared__ __align__(16) __half2 sB[2][16][SB_STR];
    int tid = threadIdx.x;
    int row0 = blockIdx.y * 128, col0 = blockIdx.x * 128;
    int warp = tid >> 5, lane = tid & 31, g = lane >> 2, tc = lane & 3;
    int wm = (warp & 3) * 32, wn = (warp >> 2) * 64;

    float acc[2][8][4];
#pragma unroll
    for (int i = 0; i < 2; i++)
#pragma unroll
        for (int j = 0; j < 8; j++)
#pragma unroll
            for (int q = 0; q < 4; q++) acc[i][j][q] = 0.f;

    int a_r0 = tid >> 2,          a_k0 = (tid & 3) * 8;
    int a_r1 = (tid + 256) >> 2,  a_k1 = ((tid + 256) & 3) * 8;
    int b_r0 = tid >> 5,          b_n0 = (tid & 31) * 4;
    int b_r1 = (tid + 256) >> 5,  b_n1 = ((tid + 256) & 31) * 4;

    uint32_t sA_base = (uint32_t)__cvta_generic_to_shared(&sA[0][0][0]);
    uint32_t sB_base = (uint32_t)__cvta_generic_to_shared(&sB[0][0][0]);

    const int ntiles = 10;

    auto issue_stage = [&](int st, int t) {
        int k0 = t * 32, k20 = t * 16;
        cpasync16(sA_base + (((st * 128 + a_r0) * SA_STR + a_k0) << 1),
                  A + (size_t)(row0 + a_r0) * KPAD + k0 + a_k0, (k0 + a_k0) < KPAD);
        cpasync16(sA_base + (((st * 128 + a_r1) * SA_STR + a_k1) << 1),
                  A + (size_t)(row0 + a_r1) * KPAD + k0 + a_k1, (k0 + a_k1) < KPAD);
        cpasync16(sB_base + (((st * 16 + b_r0) * SB_STR + b_n0) << 2),
                  Bi + (size_t)(k20 + b_r0) * N + col0 + b_n0,
                  (k20 + b_r0) < K2R && (col0 + b_n0) < N);
        cpasync16(sB_base + (((st * 16 + b_r1) * SB_STR + b_n1) << 2),
                  Bi + (size_t)(k20 + b_r1) * N + col0 + b_n1,
                  (k20 + b_r1) < K2R && (col0 + b_n1) < N);
        cp_commit();
    };

    issue_stage(0, 0);

    for (int t = 0; t < ntiles; t++) {
        int st = t & 1;
        if (t + 1 < ntiles) { issue_stage(st ^ 1, t + 1); cp_wait<1>(); }
        else                { cp_wait<0>(); }
        __syncthreads();

#pragma unroll
        for (int ks = 0; ks < 2; ks++) {
            int kb = ks * 16;
            uint32_t a[2][4];
#pragma unroll
            for (int ma = 0; ma < 2; ma++) {
                int r = wm + ma * 16;
                a[ma][0] = *reinterpret_cast<const uint32_t*>(&sA[st][r + g    ][kb + 2 * tc]);
                a[ma][1] = *reinterpret_cast<const uint32_t*>(&sA[st][r + g + 8][kb + 2 * tc]);
                a[ma][2] = *reinterpret_cast<const uint32_t*>(&sA[st][r + g    ][kb + 2 * tc + 8]);
                a[ma][3] = *reinterpret_cast<const uint32_t*>(&sA[st][r + g + 8][kb + 2 * tc + 8]);
            }
#pragma unroll
            for (int na = 0; na < 8; na++) {
                int c = wn + na * 8 + g;
                uint32_t b0 = *reinterpret_cast<const uint32_t*>(&sB[st][ks * 8 + tc    ][c]);
                uint32_t b1 = *reinterpret_cast<const uint32_t*>(&sB[st][ks * 8 + tc + 4][c]);
#pragma unroll
                for (int ma = 0; ma < 2; ma++)
                    mma16(acc[ma][na], a[ma], b0, b1);
            }
        }
        __syncthreads();
    }

#pragma unroll
    for (int ma = 0; ma < 2; ma++) {
#pragma unroll
        for (int na = 0; na < 8; na++) {
            int r = row0 + wm + ma * 16 + g;
            int c = col0 + wn + na * 8 + 2 * tc;
            if (c < N) {
                *reinterpret_cast<__half2*>(Ch + (size_t)r * N + c) =
                    __floats2half2_rn(acc[ma][na][0], acc[ma][na][1]);
                *reinterpret_cast<__half2*>(Ch + (size_t)(r + 8) * N + c) =
                    __floats2half2_rn(acc[ma][na][2], acc[ma][na][3]);
            }
        }
    }
}

// ---------------- fused group-specialized quarter-split fp16 pool ----------------
template<int W>
__device__ __forceinline__ void pool_body(const int* __restrict__ x, int bid, int tid) {
    int qt = bid & 3, n = bid >> 2;
    const int4* xs4 = reinterpret_cast<const int4*>(x + n * cL);
    constexpr int cbase = (W == 3) ? 0 : (W == 4) ? 300 : 700;
    int c0 = cbase + 2 * tid;
    int base = qt * 64;
    int nblk = (qt == 3) ? 16 : 17;
    int tlo = base + W - 1;
    int thi = base + 62 + W;

    __half2 hz = __floats2half2_rn(0.f, 0.f);
    __half2 q0 = hz, q1 = hz, q2 = hz, q3 = hz;
    __half2 m = __floats2half2_rn(-60000.f, -60000.f);

#pragma unroll 1
    for (int blk = 0; blk < nblk; blk++) {
        int4 xq = xs4[qt * 16 + blk];
#pragma unroll
        for (int u = 0; u < 4; u++) {
            int t = base + blk * 4 + u;
            int xt = (u == 0) ? xq.x : (u == 1) ? xq.y : (u == 2) ? xq.z : xq.w;
            const __half2* wp = reinterpret_cast<const __half2*>(g_WPh + (size_t)xt * cNC + c0);
            bool emit = (t >= tlo) && (t <= thi);
            if (W == 3) {
                __half2 v0 = wp[0], v1 = wp[50], v2 = wp[100];
                if (emit) m = __hmax2(m, __hadd2(q1, v2));
                q1 = __hadd2(q0, v1);
                q0 = v0;
            } else if (W == 4) {
                __half2 v0 = wp[0], v1 = wp[50], v2 = wp[100], v3 = wp[150];
                if (emit) m = __hmax2(m, __hadd2(q2, v3));
                q2 = __hadd2(q1, v2);
                q1 = __hadd2(q0, v1);
                q0 = v0;
            } else {
                __half2 v0 = wp[0], v1 = wp[50], v2 = wp[100], v3 = wp[150], v4 = wp[200];
                if (emit) m = __hmax2(m, __hadd2(q3, v4));
                q3 = __hadd2(q2, v3);
                q2 = __hadd2(q1, v2);
                q1 = __hadd2(q0, v1);
                q0 = v0;
            }
        }
    }
    g_poolpart[qt][n][(W - 3) * 50 + tid] = m;
}

__global__ __launch_bounds__(64) void pool_all(const int* __restrict__ x) {
    int bid = blockIdx.x;
    int tid = threadIdx.x;
    if (tid >= 50) return;
    const int per = cNU * 4;
    if (bid < per)            pool_body<3>(x, bid, tid);
    else if (bid < 2 * per)   pool_body<4>(x, bid - per, tid);
    else                      pool_body<5>(x, bid - 2 * per, tid);
}

// ---------------- pool combine ----------------
__global__ void feat_finish(const int* __restrict__ u_idx, const int* __restrict__ lid,
                            const float* __restrict__ b3, const float* __restrict__ b4,
                            const float* __restrict__ b5, const float* __restrict__ pos_W,
                            __half* __restrict__ feat) {
    int i = blockIdx.x * blockDim.x + threadIdx.x;
    if (i >= cNU * 150) return;
    int n = i / 150, c2 = i % 150;
    __half2 m = __hmax2(__hmax2(g_poolpart[0][n][c2], g_poolpart[1][n][c2]),
                        __hmax2(g_poolpart[2][n][c2], g_poolpart[3][n][c2]));
    int grp = c2 / 50, f2 = c2 % 50;
    int oc = grp * 100 + 2 * f2;
    const float* bb = (grp == 0) ? b3 : (grp == 1) ? b4 : b5;
    float2 bv = *reinterpret_cast<const float2*>(bb + 2 * f2);
    float2 pw = *reinterpret_cast<const float2*>(pos_W + lid[n] * cD + oc);
    float2 mf = __half22float2(m);
    *reinterpret_cast<__half2*>(feat + (size_t)u_idx[n] * KPAD + oc) =
        __floats2half2_rn(mf.x + bv.x + pw.x, mf.y + bv.y + pw.y);
}

// ---------------- fused GAT aggregate (fp16 ZR, deg-split 2 groups) ----------------
__global__ __launch_bounds__(320) void gat_aggregate(
        const int* __restrict__ src, const float* __restrict__ bmean,
        __half* __restrict__ hout) {
    __shared__ int    s_src[64];
    __shared__ float  s_alpha[cH][64];
    __shared__ float  s_er[cH];
    __shared__ float2 s_part[152];
    int n = blockIdx.x, tid = threadIdx.x;
    int rs = g_csr_off[n], re = g_csr_off[n + 1];
    int deg = re - rs;
    if (tid < cH)
        s_er[tid] = __half2float(g_ZRh[(size_t)n * PKW + ZD + cD + cH + tid]);
    __syncthreads();
    for (int i = tid; i < deg; i += 320) {
        int e = g_csr_edge[rs + i];
        int sn = src[e];
        s_src[i] = sn;
        const __half* elp = g_ZRh + (size_t)sn * PKW + ZD + cD;
#pragma unroll
        for (int h = 0; h < cH; h++) {
            float v = __half2float(elp[h]) + s_er[h];
            v = v > 0.f ? v : 0.2f * v;
            s_alpha[h][i] = expf(v);
        }
    }
    __syncthreads();
    if (tid < 160) {
        int h = tid >> 5, ln = tid & 31;
        float s = 0.f;
        for (int i = ln; i < deg; i += 32) s += s_alpha[h][i];
#pragma unroll
        for (int o = 16; o; o >>= 1) s += __shfl_xor_sync(0xffffffffu, s, o);
        float inv = 1.f / s;
        for (int i = ln; i < deg; i += 32) s_alpha[h][i] *= inv;
    }
    __syncthreads();
    // deg-split accumulation: group 0 takes even i, group 1 odd i
    int grp = tid / 160, p = tid % 160;
    float sx = 0.f, sy = 0.f;
    if (p < 150) {
        for (int i = grp; i < deg; i += 2) {
            const __half2* zp =
                reinterpret_cast<const __half2*>(g_ZRh + (size_t)s_src[i] * PKW) + p;
#pragma unroll
            for (int h = 0; h < cH; h++) {
                float2 v = __half22float2(zp[h * 150]);
                float a = s_alpha[h][i];
                sx = fmaf(a, v.x, sx);
                sy = fmaf(a, v.y, sy);
            }
        }
        if (grp == 1) s_part[p] = make_float2(sx, sy);
    }
    __syncthreads();
    if (grp == 0 && p < 150) {
        float2 o = s_part[p];
        sx += o.x;
        sy += o.y;
        float2 rm = __half22float2(
            reinterpret_cast<const __half2*>(g_ZRh + (size_t)n * PKW)[750 + p]);
        float2 bm = *reinterpret_cast<const float2*>(bmean + 2 * p);
        *reinterpret_cast<__half2*>(hout + (size_t)n * KPAD + 2 * p) =
            __floats2half2_rn(0.2f * sx + rm.x + bm.x, 0.2f * sy + rm.y + bm.y);
    }
}

// ---------------- per-dialogue context attention + output head ----------------
__global__ __launch_bounds__(320) void final_kernel(
    const __half* __restrict__ h, const float* __restrict__ py,
    const float* __restrict__ pa_W, const float* __restrict__ pa_b, const float* __restrict__ pa_c,
    const float* __restrict__ sa_W, const float* __restrict__ sa_b, const float* __restrict__ sa_c,
    const float* __restrict__ v_W, const float* __restrict__ v_b,
    const float* __restrict__ out_W, const float* __restrict__ out_b,
    float* __restrict__ out) {
    __shared__ float rows[8][cD];
    __shared__ float score[64];
    __shared__ float avec[64];
    __shared__ float px[cD];
    __shared__ float warpred[10];
    int b = blockIdx.x, tid = threadIdx.x;
    int lane = tid & 31;
    int base = b * (cU + cP);
    bool valid = tid < cD;
    int dc = valid ? tid : (cD - 1);

    for (int i = tid; i < cP * cD; i += 320)
        rows[i / cD][i % cD] = __half2float(h[(size_t)(base + cU + i / cD) * KPAD + (i % cD)]);
    if (tid < 64) score[tid] = 0.f;
    __syncthreads();
    {
        float acc[cP];
#pragma unroll
        for (int k = 0; k < cP; k++) acc[k] = pa_b[dc];
        for (int j = 0; j < cD; j++) {
            float w = pa_W[j * cD + dc];
#pragma unroll
            for (int k = 0; k < cP; k++) acc[k] += rows[k][j] * w;
        }
        float cv = pa_c[dc];
#pragma unroll
        for (int k = 0; k < cP; k++) {
            float v = valid ? tanhf(acc[k]) * cv : 0.f;
#pragma unroll
            for (int o = 16; o; o >>= 1) v += __shfl_xor_sync(0xffffffffu, v, o);
            if (lane == 0) atomicAdd(&score[k], v);
        }
    }
    __syncthreads();
    if (tid == 0) {
        float m = score[0];
        for (int k = 1; k < cP; k++) m = fmaxf(m, score[k]);
        float s = 0.f;
        for (int k = 0; k < cP; k++) { float e = expf(score[k] - m); avec[k] = e; s += e; }
        float inv = 1.f / s;
        for (int k = 0; k < cP; k++) avec[k] *= inv;
    }
    __syncthreads();
    if (valid) {
        float s = 0.f;
#pragma unroll
        for (int k = 0; k < cP; k++) s += avec[k] * rows[k][tid];
        px[tid] = s;
    }
    __syncthreads();

    if (tid < 64) score[tid] = 0.f;
    for (int ch = 0; ch < 8; ch++) {
        __syncthreads();
        for (int i = tid; i < 8 * cD; i += 320)
            rows[i / cD][i % cD] = __half2float(h[(size_t)(base + ch * 8 + i / cD) * KPAD + (i % cD)]);
        __syncthreads();
        float acc[8];
#pragma unroll
        for (int k = 0; k < 8; k++) acc[k] = sa_b[dc];
        for (int j = 0; j < cD; j++) {
            float w = sa_W[j * cD + dc];
#pragma unroll
            for (int k = 0; k < 8; k++) acc[k] += rows[k][j] * w;
        }
        float cv = sa_c[dc];
#pragma unroll
        for (int k = 0; k < 8; k++) {
            float v = valid ? tanhf(acc[k]) * cv : 0.f;
#pragma unroll
            for (int o = 16; o; o >>= 1) v += __shfl_xor_sync(0xffffffffu, v, o);
            if (lane == 0) atomicAdd(&score[ch * 8 + k], v);
        }
    }
    __syncthreads();
    if (tid == 0) {
        float m = score[0];
        for (int k = 1; k < 64; k++) m = fmaxf(m, score[k]);
        float s = 0.f;
        for (int k = 0; k < 64; k++) { float e = expf(score[k] - m); avec[k] = e; s += e; }
        float inv = 1.f / s;
        for (int k = 0; k < 64; k++) avec[k] *= inv;
    }
    __syncthreads();
    float part = 0.f;
    if (valid) {
        float sx = 0.f;
        for (int k = 0; k < 64; k++)
            sx += avec[k] * __half2float(h[(size_t)(base + k) * KPAD + tid]);
        float vx = py[b] * v_W[tid] + v_b[tid];
        part = px[tid] * out_W[tid] + sx * out_W[cD + tid] + vx * out_W[2 * cD + tid];
    }
#pragma unroll
    for (int o = 16; o; o >>= 1) part += __shfl_xor_sync(0xffffffffu, part, o);
    if (lane == 0) warpred[tid >> 5] = part;
    __syncthreads();
    if (tid == 0) {
        float s = out_b[0];
        for (int w = 0; w < 10; w++) s += warpred[w];
        out[b] = s;
    }
}

// ---------------- host launcher ----------------
extern "C" void kernel_launch(void* const* d_in, const int* in_sizes, int n_in,
                              void* d_out, int out_size) {
    const int*   x       = (const int*)d_in[0];
    const int*   src     = (const int*)d_in[1];
    const int*   dst     = (const int*)d_in[2];
    const int*   u_idx   = (const int*)d_in[3];
    const int*   q_idx   = (const int*)d_in[4];
    const int*   lid     = (const int*)d_in[5];
    const int*   pids    = (const int*)d_in[6];
    const float* py      = (const float*)d_in[7];
    const float* word_W  = (const float*)d_in[8];
    const float* conv_w3 = (const float*)d_in[9];
    const float* conv_b3 = (const float*)d_in[10];
    const float* conv_w4 = (const float*)d_in[11];
    const float* conv_b4 = (const float*)d_in[12];
    const float* conv_w5 = (const float*)d_in[13];
    const float* conv_b5 = (const float*)d_in[14];
    const float* party_W = (const float*)d_in[15];
    const float* pos_W   = (const float*)d_in[16];
    const float* gat_fc  = (const float*)d_in[17];
    const float* gat_al  = (const float*)d_in[18];
    const float* gat_ar  = (const float*)d_in[19];
    const float* gat_res = (const float*)d_in[20];
    const float* gat_b   = (const float*)d_in[21];
    const float* pa_W    = (const float*)d_in[22];
    const float* pa_b    = (const float*)d_in[23];
    const float* pa_c    = (const float*)d_in[24];
    const float* sa_W    = (const float*)d_in[25];
    const float* sa_b    = (const float*)d_in[26];
    const float* sa_c    = (const float*)d_in[27];
    const float* v_W     = (const float*)d_in[28];
    const float* v_b     = (const float*)d_in[29];
    const float* out_W   = (const float*)d_in[30];
    const float* out_b   = (const float*)d_in[31];
    float* out = (float*)d_out;

    __half *pAh, *pWPh, *ph0, *ph1, *pZRh;
    __half2 *pWcatI, *pWpackI;
    float *pbmean;
    cudaGetSymbolAddress((void**)&pAh,     g_Ah);
    cudaGetSymbolAddress((void**)&pWPh,    g_WPh);
    cudaGetSymbolAddress((void**)&pWcatI,  g_WcatI);
    cudaGetSymbolAddress((void**)&pWpackI, g_WpackI);
    cudaGetSymbolAddress((void**)&ph0,     g_h0);
    cudaGetSymbolAddress((void**)&ph1,     g_h1);
    cudaGetSymbolAddress((void**)&pZRh,    g_ZRh);
    cudaGetSymbolAddress((void**)&pbmean,  g_bmean);

    // 1: fused prep (w2h, wcat, packs, bias, pads, party feats, CSR)
    prep<<<PREP_TOTAL, 256>>>(word_W, conv_w3, conv_w4, conv_w5,
                              gat_fc, gat_res, gat_al, gat_ar, gat_b,
                              q_idx, pids, party_W, dst);
    // 2: WP GEMM
    {
        dim3 g((cNC + 127) / 128, cV / 128);
        gemm_f16<<<g, 256>>>(pAh, pWcatI, pWPh, cV, cNC);
    }
    // 3: pool
    pool_all<<<cNU * 4 * 3, 64>>>(x);
    // 4: pool combine
    feat_finish<<<(cNU * 150 + 255) / 256, 256>>>(u_idx, lid, conv_b3, conv_b4,
                                                  conv_b5, pos_W, ph0);

    // 5..14: S GAT steps
    __half* hc = ph0;
    for (int i = 0; i < cS; i++) {
        dim3 g((PKW + 127) / 128, cNT / 128);
        gemm_f16<<<g, 256>>>(hc, pWpackI + (size_t)i * K2R * PKW, pZRh, cNT, PKW);
        __half* hn = (hc == ph0) ? ph1 : ph0;
        gat_aggregate<<<cNT, 320>>>(src, pbmean + i * cD, hn);
        hc = hn;
    }

    // 15: head
    final_kernel<<<cB, 320>>>(hc, py, pa_W, pa_b, pa_c, sa_W, sa_b, sa_c,
                              v_W, v_b, out_W, out_b, out);
}

// round 17
// speedup vs baseline: 1.0034x; 1.0034x over previous
#include <cuda_runtime.h>
#include <cuda_fp16.h>
#include <math.h>
#include <stdint.h>

// ---------------- problem constants ----------------
#define cB  32
#define cU  64
#define cP  8
#define cV  32000
#define cD  300
#define cL  256
#define cH  5
#define cS  5
#define cNT 2304
#define cNU 2048
#define cNQ 256
#define cE  8128
#define cNC 1200
#define ZD  1500
#define PKL 1810
#define PKW 1824
#define KPAD 304
#define K2R 150

// ---------------- scratch (device globals) ----------------
__device__ __half  g_Ah[(size_t)cV * KPAD];
__device__ __half  g_WPh[(size_t)cV * cNC];      // 76.8 MB, L2-resident
__device__ __half2 g_WcatI[K2R * cNC];
__device__ __half2 g_WpackI[cS * K2R * PKW];
__device__ float   g_bmean[cS * cD];
__device__ __half  g_h0[cNT * KPAD];
__device__ __half  g_h1[cNT * KPAD];
__device__ __half  g_ZRh[(size_t)cNT * PKW];
__device__ __half2 g_poolpart[4][cNU][152];
__device__ int     g_csr_off[cNT + 1];
__device__ int     g_csr_edge[cE];

// ---------------- fused prep mega-kernel ----------------
#define NB(x) (((x) + 255) / 256)
#define PREP_A NB(cV * KPAD)
#define PREP_B NB(K2R * cNC)
#define PREP_C NB(cS * K2R * ZD)
#define PREP_D NB(cS * K2R * cD)
#define PREP_E NB(cS * K2R * cH * 2 * 32)
#define PREP_F NB(cS * K2R * (PKW - PKL))
#define PREP_G NB(cS * cD)
#define PREP_H NB(cNT * (KPAD - cD) * 2)
#define PREP_I NB(cNQ * cD)
#define PREP_J 1
#define PREP_TOTAL (PREP_A+PREP_B+PREP_C+PREP_D+PREP_E+PREP_F+PREP_G+PREP_H+PREP_I+PREP_J)

__device__ __forceinline__ float wcat_val(const float* w3, const float* w4,
                                          const float* w5, int k, int c) {
    if (c < 300)      { int t = c / 100,        f = c % 100;          return w3[(f * 3 + t) * cD + k]; }
    else if (c < 700) { int t = (c - 300) / 100, f = (c - 300) % 100; return w4[(f * 4 + t) * cD + k]; }
    else              { int t = (c - 700) / 100, f = (c - 700) % 100; return w5[(f * 5 + t) * cD + k]; }
}

__global__ __launch_bounds__(256) void prep(
        const float* __restrict__ word_W,
        const float* __restrict__ w3, const float* __restrict__ w4,
        const float* __restrict__ w5,
        const float* __restrict__ fc, const float* __restrict__ res,
        const float* __restrict__ al, const float* __restrict__ ar,
        const float* __restrict__ gb,
        const int* __restrict__ q_idx, const int* __restrict__ pids,
        const float* __restrict__ party_W,
        const int* __restrict__ dst) {
    __shared__ int cnt[cNT];
    __shared__ int off[cNT];
    __shared__ int ws[256];
    int bid = blockIdx.x, tid = threadIdx.x;
    if (bid < PREP_A) {                                   // w2h
        int i = bid * 256 + tid;
        if (i < cV * KPAD) {
            int r = i / KPAD, k = i % KPAD;
            g_Ah[i] = (k < cD) ? __float2half(word_W[(size_t)r * cD + k]) : __half(0.f);
        }
        return;
    }
    bid -= PREP_A;
    if (bid < PREP_B) {                                   // wcat
        int i = bid * 256 + tid;
        if (i < K2R * cNC) {
            int k2 = i / cNC, c = i % cNC;
            g_WcatI[i] = __floats2half2_rn(wcat_val(w3, w4, w5, 2 * k2, c),
                                           wcat_val(w3, w4, w5, 2 * k2 + 1, c));
        }
        return;
    }
    bid -= PREP_B;
    if (bid < PREP_C) {                                   // pack_z
        int i = bid * 256 + tid;
        if (i < cS * K2R * ZD) {
            int s = i / (K2R * ZD);
            int k2 = (i / ZD) % K2R;
            int c = i % ZD;
            const float* f0 = fc + (size_t)s * cD * ZD + (size_t)(2 * k2) * ZD;
            g_WpackI[(size_t)(s * K2R + k2) * PKW + c] = __floats2half2_rn(f0[c], f0[ZD + c]);
        }
        return;
    }
    bid -= PREP_C;
    if (bid < PREP_D) {                                   // pack_rmean
        int i = bid * 256 + tid;
        if (i < cS * K2R * cD) {
            int s = i / (K2R * cD);
            int k2 = (i / cD) % K2R;
            int d = i % cD;
            const float* r0 = res + (size_t)s * cD * ZD + (size_t)(2 * k2) * ZD;
            float s0 = 0.f, s1 = 0.f;
#pragma unroll
            for (int h = 0; h < cH; h++) { s0 += r0[h * cD + d]; s1 += r0[ZD + h * cD + d]; }
            g_WpackI[(size_t)(s * K2R + k2) * PKW + ZD + d] =
                __floats2half2_rn(0.2f * s0, 0.2f * s1);
        }
        return;
    }
    bid -= PREP_D;
    if (bid < PREP_E) {                                   // pack_elr
        int w = (bid * 256 + tid) >> 5;
        int lane = tid & 31;
        if (w < cS * K2R * cH * 2) {
            int side = w & 1;
            int h = (w >> 1) % cH;
            int k2 = (w >> 1) / cH % K2R;
            int s = (w >> 1) / (cH * K2R);
            const float* av = (side ? ar : al) + (size_t)s * cH * cD + h * cD;
            const float* f0 = fc + (size_t)s * cD * ZD + (size_t)(2 * k2) * ZD + h * cD;
            float s0 = 0.f, s1 = 0.f;
            for (int d = lane; d < cD; d += 32) {
                float a = av[d];
                s0 += f0[d] * a;
                s1 += f0[ZD + d] * a;
            }
#pragma unroll
            for (int o = 16; o; o >>= 1) {
                s0 += __shfl_xor_sync(0xffffffffu, s0, o);
                s1 += __shfl_xor_sync(0xffffffffu, s1, o);
            }
            if (lane == 0)
                g_WpackI[(size_t)(s * K2R + k2) * PKW + ZD + cD + side * cH + h] =
                    __floats2half2_rn(s0, s1);
        }
        return;
    }
    bid -= PREP_E;
    if (bid < PREP_F) {                                   // pack_pad
        int i = bid * 256 + tid;
        if (i < cS * K2R * (PKW - PKL)) {
            int s = i / (K2R * (PKW - PKL));
            int k2 = (i / (PKW - PKL)) % K2R;
            int c = i % (PKW - PKL);
            g_WpackI[(size_t)(s * K2R + k2) * PKW + PKL + c] = __floats2half2_rn(0.f, 0.f);
        }
        return;
    }
    bid -= PREP_F;
    if (bid < PREP_G) {                                   // bias_mean
        int i = bid * 256 + tid;
        if (i < cS * cD) {
            int s = i / cD, d = i % cD;
            float sum = 0.f;
#pragma unroll
            for (int h = 0; h < cH; h++) sum += gb[s * ZD + h * cD + d];
            g_bmean[i] = 0.2f * sum;
        }
        return;
    }
    bid -= PREP_G;
    if (bid < PREP_H) {                                   // hzero_pads
        int i = bid * 256 + tid;
        if (i < cNT * (KPAD - cD) * 2) {
            int buf = i & 1;
            int j = i >> 1;
            int n = j / (KPAD - cD), d = cD + j % (KPAD - cD);
            (buf ? g_h1 : g_h0)[(size_t)n * KPAD + d] = __half(0.f);
        }
        return;
    }
    bid -= PREP_H;
    if (bid < PREP_I) {                                   // party features
        int i = bid * 256 + tid;
        if (i < cNQ * cD) {
            int j = i / cD, d = i % cD;
            g_h0[(size_t)q_idx[j] * KPAD + d] = __float2half(party_W[pids[j] * cD + d]);
        }
        return;
    }
    // ---- csr build (single block) ----
    {
        int t = tid;
        for (int i = t; i < cNT; i += 256) cnt[i] = 0;
        __syncthreads();
        for (int e = t; e < cE; e += 256) atomicAdd(&cnt[dst[e]], 1);
        __syncthreads();
        int base = t * 9;
        int c[9]; int sum = 0;
#pragma unroll
        for (int j = 0; j < 9; j++) { c[j] = sum; sum += cnt[base + j]; }
        ws[t] = sum;
        __syncthreads();
        for (int o = 1; o < 256; o <<= 1) {
            int v = (t >= o) ? ws[t - o] : 0;
            __syncthreads();
            ws[t] += v;
            __syncthreads();
        }
        int pre = ws[t] - sum;
#pragma unroll
        for (int j = 0; j < 9; j++) { off[base + j] = pre + c[j]; g_csr_off[base + j] = pre + c[j]; }
        if (t == 255) g_csr_off[cNT] = pre + sum;
        __syncthreads();
        for (int i = t; i < cNT; i += 256) cnt[i] = 0;
        __syncthreads();
        for (int e = t; e < cE; e += 256) {
            int dn = dst[e];
            int p = off[dn] + atomicAdd(&cnt[dn], 1);
            g_csr_edge[p] = e;
        }
    }
}

// ---------------- fp16 GEMM helpers ----------------
__device__ __forceinline__ void mma16(float* c, const uint32_t* a, uint32_t b0, uint32_t b1) {
    asm volatile(
        "mma.sync.aligned.m16n8k16.row.col.f32.f16.f16.f32 "
        "{%0,%1,%2,%3},{%4,%5,%6,%7},{%8,%9},{%0,%1,%2,%3};"
        : "+f"(c[0]), "+f"(c[1]), "+f"(c[2]), "+f"(c[3])
        : "r"(a[0]), "r"(a[1]), "r"(a[2]), "r"(a[3]), "r"(b0), "r"(b1));
}
__device__ __forceinline__ void cpasync16(uint32_t dst, const void* src, bool valid) {
    int sz = valid ? 16 : 0;
    asm volatile("cp.async.ca.shared.global [%0], [%1], 16, %2;"
                 :: "r"(dst), "l"(src), "r"(sz));
}
__device__ __forceinline__ void cp_commit() { asm volatile("cp.async.commit_group;"); }
template<int N>
__device__ __forceinline__ void cp_wait() { asm volatile("cp.async.wait_group %0;" :: "n"(N)); }

// ---------------- fp16 tensor-core GEMM, cp.async 3-stage ----------------
#define SA_STR 40
#define SB_STR 132
__global__ __launch_bounds__(256, 2) void gemm_f16(
        const __half* __restrict__ A, const __half2* __restrict__ Bi,
        __half* __restrict__ Ch, int M, int N) {
    __shared__ __align__(16) __half  sA[3][128][SA_STR];
    __shared__ __align__(16) __half2 sB[3][16][SB_STR];
    int tid = threadIdx.x;
    int row0 = blockIdx.y * 128, col0 = blockIdx.x * 128;
    int warp = tid >> 5, lane = tid & 31, g = lane >> 2, tc = lane & 3;
    int wm = (warp & 3) * 32, wn = (warp >> 2) * 64;

    float acc[2][8][4];
#pragma unroll
    for (int i = 0; i < 2; i++)
#pragma unroll
        for (int j = 0; j < 8; j++)
#pragma unroll
            for (int q = 0; q < 4; q++) acc[i][j][q] = 0.f;

    int a_r0 = tid >> 2,          a_k0 = (tid & 3) * 8;
    int a_r1 = (tid + 256) >> 2,  a_k1 = ((tid + 256) & 3) * 8;
    int b_r0 = tid >> 5,          b_n0 = (tid & 31) * 4;
    int b_r1 = (tid + 256) >> 5,  b_n1 = ((tid + 256) & 31) * 4;

    uint32_t sA_base = (uint32_t)__cvta_generic_to_shared(&sA[0][0][0]);
    uint32_t sB_base = (uint32_t)__cvta_generic_to_shared(&sB[0][0][0]);

    const int ntiles = 10;

    auto issue_stage = [&](int st, int t) {
        int k0 = t * 32, k20 = t * 16;
        cpasync16(sA_base + (((st * 128 + a_r0) * SA_STR + a_k0) << 1),
                  A + (size_t)(row0 + a_r0) * KPAD + k0 + a_k0, (k0 + a_k0) < KPAD);
        cpasync16(sA_base + (((st * 128 + a_r1) * SA_STR + a_k1) << 1),
                  A + (size_t)(row0 + a_r1) * KPAD + k0 + a_k1, (k0 + a_k1) < KPAD);
        cpasync16(sB_base + (((st * 16 + b_r0) * SB_STR + b_n0) << 2),
                  Bi + (size_t)(k20 + b_r0) * N + col0 + b_n0,
                  (k20 + b_r0) < K2R && (col0 + b_n0) < N);
        cpasync16(sB_base + (((st * 16 + b_r1) * SB_STR + b_n1) << 2),
                  Bi + (size_t)(k20 + b_r1) * N + col0 + b_n1,
                  (k20 + b_r1) < K2R && (col0 + b_n1) < N);
        cp_commit();
    };

    issue_stage(0, 0);
    issue_stage(1, 1);

    for (int t = 0; t < ntiles; t++) {
        int st = t % 3;
        if (t + 2 < ntiles) { issue_stage((t + 2) % 3, t + 2); cp_wait<2>(); }
        else if (t + 1 < ntiles) { cp_wait<1>(); }
        else { cp_wait<0>(); }
        __syncthreads();

#pragma unroll
        for (int ks = 0; ks < 2; ks++) {
            int kb = ks * 16;
            uint32_t a[2][4];
#pragma unroll
            for (int ma = 0; ma < 2; ma++) {
                int r = wm + ma * 16;
                a[ma][0] = *reinterpret_cast<const uint32_t*>(&sA[st][r + g    ][kb + 2 * tc]);
                a[ma][1] = *reinterpret_cast<const uint32_t*>(&sA[st][r + g + 8][kb + 2 * tc]);
                a[ma][2] = *reinterpret_cast<const uint32_t*>(&sA[st][r + g    ][kb + 2 * tc + 8]);
                a[ma][3] = *reinterpret_cast<const uint32_t*>(&sA[st][r + g + 8][kb + 2 * tc + 8]);
            }
#pragma unroll
            for (int na = 0; na < 8; na++) {
                int c = wn + na * 8 + g;
                uint32_t b0 = *reinterpret_cast<const uint32_t*>(&sB[st][ks * 8 + tc    ][c]);
                uint32_t b1 = *reinterpret_cast<const uint32_t*>(&sB[st][ks * 8 + tc + 4][c]);
#pragma unroll
                for (int ma = 0; ma < 2; ma++)
                    mma16(acc[ma][na], a[ma], b0, b1);
            }
        }
        __syncthreads();
    }

#pragma unroll
    for (int ma = 0; ma < 2; ma++) {
#pragma unroll
        for (int na = 0; na < 8; na++) {
            int r = row0 + wm + ma * 16 + g;
            int c = col0 + wn + na * 8 + 2 * tc;
            if (c < N) {
                *reinterpret_cast<__half2*>(Ch + (size_t)r * N + c) =
                    __floats2half2_rn(acc[ma][na][0], acc[ma][na][1]);
                *reinterpret_cast<__half2*>(Ch + (size_t)(r + 8) * N + c) =
                    __floats2half2_rn(acc[ma][na][2], acc[ma][na][3]);
            }
        }
    }
}

// ---------------- fused group-specialized quarter-split fp16 pool ----------------
template<int W>
__device__ __forceinline__ void pool_body(const int* __restrict__ x, int bid, int tid) {
    int qt = bid & 3, n = bid >> 2;
    const int4* xs4 = reinterpret_cast<const int4*>(x + n * cL);
    constexpr int cbase = (W == 3) ? 0 : (W == 4) ? 300 : 700;
    int c0 = cbase + 2 * tid;
    int base = qt * 64;
    int nblk = (qt == 3) ? 16 : 17;
    int tlo = base + W - 1;
    int thi = base + 62 + W;

    __half2 hz = __floats2half2_rn(0.f, 0.f);
    __half2 q0 = hz, q1 = hz, q2 = hz, q3 = hz;
    __half2 m = __floats2half2_rn(-60000.f, -60000.f);

#pragma unroll 1
    for (int blk = 0; blk < nblk; blk++) {
        int4 xq = xs4[qt * 16 + blk];
#pragma unroll
        for (int u = 0; u < 4; u++) {
            int t = base + blk * 4 + u;
            int xt = (u == 0) ? xq.x : (u == 1) ? xq.y : (u == 2) ? xq.z : xq.w;
            const __half2* wp = reinterpret_cast<const __half2*>(g_WPh + (size_t)xt * cNC + c0);
            bool emit = (t >= tlo) && (t <= thi);
            if (W == 3) {
                __half2 v0 = wp[0], v1 = wp[50], v2 = wp[100];
                if (emit) m = __hmax2(m, __hadd2(q1, v2));
                q1 = __hadd2(q0, v1);
                q0 = v0;
            } else if (W == 4) {
                __half2 v0 = wp[0], v1 = wp[50], v2 = wp[100], v3 = wp[150];
                if (emit) m = __hmax2(m, __hadd2(q2, v3));
                q2 = __hadd2(q1, v2);
                q1 = __hadd2(q0, v1);
                q0 = v0;
            } else {
                __half2 v0 = wp[0], v1 = wp[50], v2 = wp[100], v3 = wp[150], v4 = wp[200];
                if (emit) m = __hmax2(m, __hadd2(q3, v4));
                q3 = __hadd2(q2, v3);
                q2 = __hadd2(q1, v2);
                q1 = __hadd2(q0, v1);
                q0 = v0;
            }
        }
    }
    g_poolpart[qt][n][(W - 3) * 50 + tid] = m;
}

__global__ __launch_bounds__(64) void pool_all(const int* __restrict__ x) {
    int bid = blockIdx.x;
    int tid = threadIdx.x;
    if (tid >= 50) return;
    const int per = cNU * 4;
    if (bid < per)            pool_body<3>(x, bid, tid);
    else if (bid < 2 * per)   pool_body<4>(x, bid - per, tid);
    else                      pool_body<5>(x, bid - 2 * per, tid);
}

// ---------------- pool combine ----------------
__global__ void feat_finish(const int* __restrict__ u_idx, const int* __restrict__ lid,
                            const float* __restrict__ b3, const float* __restrict__ b4,
                            const float* __restrict__ b5, const float* __restrict__ pos_W,
                            __half* __restrict__ feat) {
    int i = blockIdx.x * blockDim.x + threadIdx.x;
    if (i >= cNU * 150) return;
    int n = i / 150, c2 = i % 150;
    __half2 m = __hmax2(__hmax2(g_poolpart[0][n][c2], g_poolpart[1][n][c2]),
                        __hmax2(g_poolpart[2][n][c2], g_poolpart[3][n][c2]));
    int grp = c2 / 50, f2 = c2 % 50;
    int oc = grp * 100 + 2 * f2;
    const float* bb = (grp == 0) ? b3 : (grp == 1) ? b4 : b5;
    float2 bv = *reinterpret_cast<const float2*>(bb + 2 * f2);
    float2 pw = *reinterpret_cast<const float2*>(pos_W + lid[n] * cD + oc);
    float2 mf = __half22float2(m);
    *reinterpret_cast<__half2*>(feat + (size_t)u_idx[n] * KPAD + oc) =
        __floats2half2_rn(mf.x + bv.x + pw.x, mf.y + bv.y + pw.y);
}

// ---------------- fused GAT aggregate (fp16 ZR, column pairs, 160 thr) ----------------
__global__ __launch_bounds__(160) void gat_aggregate(
        const int* __restrict__ src, const float* __restrict__ bmean,
        __half* __restrict__ hout) {
    __shared__ int   s_src[64];
    __shared__ float s_alpha[cH][64];
    __shared__ float s_er[cH];
    int n = blockIdx.x, tid = threadIdx.x;
    int rs = g_csr_off[n], re = g_csr_off[n + 1];
    int deg = re - rs;
    if (tid < cH)
        s_er[tid] = __half2float(g_ZRh[(size_t)n * PKW + ZD + cD + cH + tid]);
    __syncthreads();
    for (int i = tid; i < deg; i += 160) {
        int e = g_csr_edge[rs + i];
        int sn = src[e];
        s_src[i] = sn;
        const __half* elp = g_ZRh + (size_t)sn * PKW + ZD + cD;
#pragma unroll
        for (int h = 0; h < cH; h++) {
            float v = __half2float(elp[h]) + s_er[h];
            v = v > 0.f ? v : 0.2f * v;
            s_alpha[h][i] = expf(v);
        }
    }
    __syncthreads();
    {
        int h = tid >> 5, ln = tid & 31;
        float s = 0.f;
        for (int i = ln; i < deg; i += 32) s += s_alpha[h][i];
#pragma unroll
        for (int o = 16; o; o >>= 1) s += __shfl_xor_sync(0xffffffffu, s, o);
        float inv = 1.f / s;
        for (int i = ln; i < deg; i += 32) s_alpha[h][i] *= inv;
    }
    __syncthreads();
    if (tid < 150) {
        float sx = 0.f, sy = 0.f;
        for (int i = 0; i < deg; i++) {
            const __half2* zp =
                reinterpret_cast<const __half2*>(g_ZRh + (size_t)s_src[i] * PKW) + tid;
#pragma unroll
            for (int h = 0; h < cH; h++) {
                float2 v = __half22float2(zp[h * 150]);
                float a = s_alpha[h][i];
                sx = fmaf(a, v.x, sx);
                sy = fmaf(a, v.y, sy);
            }
        }
        float2 rm = __half22float2(
            reinterpret_cast<const __half2*>(g_ZRh + (size_t)n * PKW)[750 + tid]);
        float2 bm = *reinterpret_cast<const float2*>(bmean + 2 * tid);
        *reinterpret_cast<__half2*>(hout + (size_t)n * KPAD + 2 * tid) =
            __floats2half2_rn(0.2f * sx + rm.x + bm.x, 0.2f * sy + rm.y + bm.y);
    }
}

// ---------------- per-dialogue context attention + output head ----------------
__global__ __launch_bounds__(320) void final_kernel(
    const __half* __restrict__ h, const float* __restrict__ py,
    const float* __restrict__ pa_W, const float* __restrict__ pa_b, const float* __restrict__ pa_c,
    const float* __restrict__ sa_W, const float* __restrict__ sa_b, const float* __restrict__ sa_c,
    const float* __restrict__ v_W, const float* __restrict__ v_b,
    const float* __restrict__ out_W, const float* __restrict__ out_b,
    float* __restrict__ out) {
    __shared__ float rows[8][cD];
    __shared__ float score[64];
    __shared__ float avec[64];
    __shared__ float px[cD];
    __shared__ float warpred[10];
    int b = blockIdx.x, tid = threadIdx.x;
    int lane = tid & 31;
    int base = b * (cU + cP);
    bool valid = tid < cD;
    int dc = valid ? tid : (cD - 1);

    for (int i = tid; i < cP * cD; i += 320)
        rows[i / cD][i % cD] = __half2float(h[(size_t)(base + cU + i / cD) * KPAD + (i % cD)]);
    if (tid < 64) score[tid] = 0.f;
    __syncthreads();
    {
        float acc[cP];
#pragma unroll
        for (int k = 0; k < cP; k++) acc[k] = pa_b[dc];
        for (int j = 0; j < cD; j++) {
            float w = pa_W[j * cD + dc];
#pragma unroll
            for (int k = 0; k < cP; k++) acc[k] += rows[k][j] * w;
        }
        float cv = pa_c[dc];
#pragma unroll
        for (int k = 0; k < cP; k++) {
            float v = valid ? tanhf(acc[k]) * cv : 0.f;
#pragma unroll
            for (int o = 16; o; o >>= 1) v += __shfl_xor_sync(0xffffffffu, v, o);
            if (lane == 0) atomicAdd(&score[k], v);
        }
    }
    __syncthreads();
    if (tid == 0) {
        float m = score[0];
        for (int k = 1; k < cP; k++) m = fmaxf(m, score[k]);
        float s = 0.f;
        for (int k = 0; k < cP; k++) { float e = expf(score[k] - m); avec[k] = e; s += e; }
        float inv = 1.f / s;
        for (int k = 0; k < cP; k++) avec[k] *= inv;
    }
    __syncthreads();
    if (valid) {
        float s = 0.f;
#pragma unroll
        for (int k = 0; k < cP; k++) s += avec[k] * rows[k][tid];
        px[tid] = s;
    }
    __syncthreads();

    if (tid < 64) score[tid] = 0.f;
    for (int ch = 0; ch < 8; ch++) {
        __syncthreads();
        for (int i = tid; i < 8 * cD; i += 320)
            rows[i / cD][i % cD] = __half2float(h[(size_t)(base + ch * 8 + i / cD) * KPAD + (i % cD)]);
        __syncthreads();
        float acc[8];
#pragma unroll
        for (int k = 0; k < 8; k++) acc[k] = sa_b[dc];
        for (int j = 0; j < cD; j++) {
            float w = sa_W[j * cD + dc];
#pragma unroll
            for (int k = 0; k < 8; k++) acc[k] += rows[k][j] * w;
        }
        float cv = sa_c[dc];
#pragma unroll
        for (int k = 0; k < 8; k++) {
            float v = valid ? tanhf(acc[k]) * cv : 0.f;
#pragma unroll
            for (int o = 16; o; o >>= 1) v += __shfl_xor_sync(0xffffffffu, v, o);
            if (lane == 0) atomicAdd(&score[ch * 8 + k], v);
        }
    }
    __syncthreads();
    if (tid == 0) {
        float m = score[0];
        for (int k = 1; k < 64; k++) m = fmaxf(m, score[k]);
        float s = 0.f;
        for (int k = 0; k < 64; k++) { float e = expf(score[k] - m); avec[k] = e; s += e; }
        float inv = 1.f / s;
        for (int k = 0; k < 64; k++) avec[k] *= inv;
    }
    __syncthreads();
    float part = 0.f;
    if (valid) {
        float sx = 0.f;
        for (int k = 0; k < 64; k++)
            sx += avec[k] * __half2float(h[(size_t)(base + k) * KPAD + tid]);
        float vx = py[b] * v_W[tid] + v_b[tid];
        part = px[tid] * out_W[tid] + sx * out_W[cD + tid] + vx * out_W[2 * cD + tid];
    }
#pragma unroll
    for (int o = 16; o; o >>= 1) part += __shfl_xor_sync(0xffffffffu, part, o);
    if (lane == 0) warpred[tid >> 5] = part;
    __syncthreads();
    if (tid == 0) {
        float s = out_b[0];
        for (int w = 0; w < 10; w++) s += warpred[w];
        out[b] = s;
    }
}

// ---------------- host launcher ----------------
extern "C" void kernel_launch(void* const* d_in, const int* in_sizes, int n_in,
                              void* d_out, int out_size) {
    const int*   x       = (const int*)d_in[0];
    const int*   src     = (const int*)d_in[1];
    const int*   dst     = (const int*)d_in[2];
    const int*   u_idx   = (const int*)d_in[3];
    const int*   q_idx   = (const int*)d_in[4];
    const int*   lid     = (const int*)d_in[5];
    const int*   pids    = (const int*)d_in[6];
    const float* py      = (const float*)d_in[7];
    const float* word_W  = (const float*)d_in[8];
    const float* conv_w3 = (const float*)d_in[9];
    const float* conv_b3 = (const float*)d_in[10];
    const float* conv_w4 = (const float*)d_in[11];
    const float* conv_b4 = (const float*)d_in[12];
    const float* conv_w5 = (const float*)d_in[13];
    const float* conv_b5 = (const float*)d_in[14];
    const float* party_W = (const float*)d_in[15];
    const float* pos_W   = (const float*)d_in[16];
    const float* gat_fc  = (const float*)d_in[17];
    const float* gat_al  = (const float*)d_in[18];
    const float* gat_ar  = (const float*)d_in[19];
    const float* gat_res = (const float*)d_in[20];
    const float* gat_b   = (const float*)d_in[21];
    const float* pa_W    = (const float*)d_in[22];
    const float* pa_b    = (const float*)d_in[23];
    const float* pa_c    = (const float*)d_in[24];
    const float* sa_W    = (const float*)d_in[25];
    const float* sa_b    = (const float*)d_in[26];
    const float* sa_c    = (const float*)d_in[27];
    const float* v_W     = (const float*)d_in[28];
    const float* v_b     = (const float*)d_in[29];
    const float* out_W   = (const float*)d_in[30];
    const float* out_b   = (const float*)d_in[31];
    float* out = (float*)d_out;

    __half *pAh, *pWPh, *ph0, *ph1, *pZRh;
    __half2 *pWcatI, *pWpackI;
    float *pbmean;
    cudaGetSymbolAddress((void**)&pAh,     g_Ah);
    cudaGetSymbolAddress((void**)&pWPh,    g_WPh);
    cudaGetSymbolAddress((void**)&pWcatI,  g_WcatI);
    cudaGetSymbolAddress((void**)&pWpackI, g_WpackI);
    cudaGetSymbolAddress((void**)&ph0,     g_h0);
    cudaGetSymbolAddress((void**)&ph1,     g_h1);
    cudaGetSymbolAddress((void**)&pZRh,    g_ZRh);
    cudaGetSymbolAddress((void**)&pbmean,  g_bmean);

    // 1: fused prep
    prep<<<PREP_TOTAL, 256>>>(word_W, conv_w3, conv_w4, conv_w5,
                              gat_fc, gat_res, gat_al, gat_ar, gat_b,
                              q_idx, pids, party_W, dst);
    // 2: WP GEMM
    {
        dim3 g((cNC + 127) / 128, cV / 128);
        gemm_f16<<<g, 256>>>(pAh, pWcatI, pWPh, cV, cNC);
    }
    // 3: pool
    pool_all<<<cNU * 4 * 3, 64>>>(x);
    // 4: pool combine
    feat_finish<<<(cNU * 150 + 255) / 256, 256>>>(u_idx, lid, conv_b3, conv_b4,
                                                  conv_b5, pos_W, ph0);

    // 5..14: S GAT steps
    __half* hc = ph0;
    for (int i = 0; i < cS; i++) {
        dim3 g((PKW + 127) / 128, cNT / 128);
        gemm_f16<<<g, 256>>>(hc, pWpackI + (size_t)i * K2R * PKW, pZRh, cNT, PKW);
        __half* hn = (hc == ph0) ? ph1 : ph0;
        gat_aggregate<<<cNT, 160>>>(src, pbmean + i * cD, hn);
        hc = hn;
    }

    // 15: head
    final_kernel<<<cB, 320>>>(hc, py, pa_W, pa_b, pa_c, sa_W, sa_b, sa_c,
                              v_W, v_b, out_W, out_b, out);
}